// round 10
// baseline (speedup 1.0000x reference)
#include <cuda_runtime.h>
#include <cuda_fp16.h>

#define DD 160
#define HH 160
#define WW 160
#define NB 2
#define HW_ (HH * WW)
#define HW2 (HW_ / 2)
#define DHW_ (DD * HH * WW)          // 4,096,000
#define DHW2 (DHW_ / 2)
#define NVOX (NB * DHW_)             // 8,192,000
#define DCH 8
#define DL  (DD / DCH)               // 20
#define HCH 5
#define HL  (HH / HCH)               // 32
#define NWD (NB * HH * 40 * DCH)     // 102,400 passWD threads
#define NPART 500                    // passH blocks

#define G0c 0.0125602f
#define G1c 0.0788279f
#define G2c 0.2372961f
#define G3c 0.3426315f

typedef unsigned long long u64;

__device__ __forceinline__ u64 pk(float lo, float hi) {
    u64 r; asm("mov.b64 %0, {%1, %2};" : "=l"(r) : "f"(lo), "f"(hi)); return r;
}
__device__ __forceinline__ float2 upk(u64 v) {
    float2 r; asm("mov.b64 {%0, %1}, %2;" : "=f"(r.x), "=f"(r.y) : "l"(v)); return r;
}
__device__ __forceinline__ u64 fma2(u64 a, u64 b, u64 c) {
    u64 d; asm("fma.rn.f32x2 %0, %1, %2, %3;" : "=l"(d) : "l"(a), "l"(b), "l"(c)); return d;
}
__device__ __forceinline__ u64 mul2(u64 a, u64 b) {
    u64 d; asm("mul.rn.f32x2 %0, %1, %2;" : "=l"(d) : "l"(a), "l"(b)); return d;
}
__device__ __forceinline__ u64 add2(u64 a, u64 b) {
    u64 d; asm("add.rn.f32x2 %0, %1, %2;" : "=l"(d) : "l"(a), "l"(b)); return d;
}
__device__ __forceinline__ unsigned h2u(__half2 h) {
    return *reinterpret_cast<unsigned*>(&h);
}
__device__ __forceinline__ __half2 f2h(u64 v) {
    float2 f = upk(v); return __floats2half2_rn(f.x, f.y);
}

// zero-padding valid-weight factor per axis
__device__ __forceinline__ float bfac(int i) {
    float f = 1.f;
    if (i < 3)   f -= (i == 2 ? G0c : (i == 1 ? (G0c + G1c) : (G0c + G1c + G2c)));
    if (i > 156) f -= (i == 157 ? G0c : (i == 158 ? (G0c + G1c) : (G0c + G1c + G2c)));
    return f;
}

// fp16 scratch: 5 conv-wd shifted fields x 2 batches (81.92 MB)
__device__ __half g_buf2[10u * DHW_];
__device__ float g_partials[NPART];
__device__ int g_ctr;

struct W5 { __half2 h[5][2]; };   // W-conv'd quad (4 voxels) of the 5 fields

// W-conv of the 5 shifted fields for one w-quad of one row.
// Sh[i] packs the masked -0.5 shifts (0 for out-of-range taps; loads there
// are zeroed by the wq guards, so field value becomes exactly 0).
__device__ __forceinline__ W5 wdrow(const float* __restrict__ pr,
                                    const float* __restrict__ tr,
                                    const u64* Sh, int wq) {
    const float4 z4 = {0.f, 0.f, 0.f, 0.f};
    float4 A0 = (wq > 0)  ? *(const float4*)(pr - 4) : z4;
    float4 A1 = *(const float4*)(pr);
    float4 A2 = (wq < 39) ? *(const float4*)(pr + 4) : z4;
    float4 B0 = (wq > 0)  ? *(const float4*)(tr - 4) : z4;
    float4 B1 = *(const float4*)(tr);
    float4 B2 = (wq < 39) ? *(const float4*)(tr + 4) : z4;

    float av[10] = {A0.y, A0.z, A0.w, A1.x, A1.y, A1.z, A1.w, A2.x, A2.y, A2.z};
    float bv[10] = {B0.y, B0.z, B0.w, B1.x, B1.y, B1.z, B1.w, B2.x, B2.y, B2.z};

    u64 P[9], R[9];
#pragma unroll
    for (int i = 0; i < 9; ++i) {
        P[i] = add2(pk(av[i], av[i + 1]), Sh[i]);
        R[i] = add2(pk(bv[i], bv[i + 1]), Sh[i]);
    }

    const float gs[7] = {G0c, G1c, G2c, G3c, G2c, G1c, G0c};
    u64 acc[5][2];
#pragma unroll
    for (int o = 0; o < 2; ++o) {
        u64 g = pk(gs[0], gs[0]);
        u64 p0 = P[2 * o], r0 = R[2 * o];
        acc[0][o] = mul2(g, p0);
        acc[1][o] = mul2(g, r0);
        acc[2][o] = mul2(g, mul2(p0, p0));
        acc[3][o] = mul2(g, mul2(r0, r0));
        acc[4][o] = mul2(g, mul2(p0, r0));
#pragma unroll
        for (int k = 1; k < 7; ++k) {
            u64 gk2 = pk(gs[k], gs[k]);
            u64 pp = P[k + 2 * o], rr = R[k + 2 * o];
            acc[0][o] = fma2(gk2, pp, acc[0][o]);
            acc[1][o] = fma2(gk2, rr, acc[1][o]);
            acc[2][o] = fma2(gk2, mul2(pp, pp), acc[2][o]);
            acc[3][o] = fma2(gk2, mul2(rr, rr), acc[3][o]);
            acc[4][o] = fma2(gk2, mul2(pp, rr), acc[4][o]);
        }
    }

    W5 w;
#pragma unroll
    for (int f = 0; f < 5; ++f) {
        w.h[f][0] = f2h(acc[f][0]);
        w.h[f][1] = f2h(acc[f][1]);
    }
    return w;
}

// ---------------------------------------------------------------------------
// passWD: fused W-conv (f32x2) + D-conv (HFMA2). Thread = (n, h, w-quad,
// d-chunk of 20); rolling 5x7x2 half2 d-window; planar fp16 stores. No smem.
// ---------------------------------------------------------------------------
__global__ void __launch_bounds__(128) passWD(const float* __restrict__ p,
                                              const float* __restrict__ t) {
    int tid = blockIdx.x * blockDim.x + threadIdx.x;
    if (tid >= NWD) return;
    int wq  = tid % 40;
    int rem = tid / 40;
    int ci  = rem % DCH;
    int rm2 = rem / DCH;
    int h   = rm2 % HH;
    int n   = rm2 / HH;
    int d0  = ci * DL;
    int w0  = 4 * wq;

    // masked shift constants: tap j covers w = w0-3+j, j=0..9
    u64 Sh[9];
    {
        float s[10];
#pragma unroll
        for (int j = 0; j < 10; ++j) {
            int w = w0 - 3 + j;
            s[j] = (w >= 0 && w < WW) ? -0.5f : 0.f;
        }
#pragma unroll
        for (int i = 0; i < 9; ++i) Sh[i] = pk(s[i], s[i + 1]);
    }

    const float* pp = p + (long)n * DHW_ + (long)h * WW + w0;
    const float* tt = t + (long)n * DHW_ + (long)h * WW + w0;

    const __half2 Z = __float2half2_rn(0.f);
    __half2 win[5][7][2];
#pragma unroll
    for (int k = 0; k < 7; ++k) {
        int dd = d0 - 3 + k;
        if (dd >= 0 && dd < DD) {
            W5 w = wdrow(pp + (long)dd * HW_, tt + (long)dd * HW_, Sh, wq);
#pragma unroll
            for (int f = 0; f < 5; ++f) {
                win[f][k][0] = w.h[f][0];
                win[f][k][1] = w.h[f][1];
            }
        } else {
#pragma unroll
            for (int f = 0; f < 5; ++f) { win[f][k][0] = Z; win[f][k][1] = Z; }
        }
    }

    const __half2 G0h = __float2half2_rn(G0c), G1h = __float2half2_rn(G1c);
    const __half2 G2h = __float2half2_rn(G2c), G3h = __float2half2_rn(G3c);

    const float* pc = pp + (long)(d0 + 4) * HW_;
    const float* tc = tt + (long)(d0 + 4) * HW_;
    // uint2 index: quad of 4 halves = 8 bytes
    uint2* dst = (uint2*)g_buf2 + ((long)n * DHW2 + (long)d0 * HW2 + (long)h * 80) / 2 + wq;
    const long FS = (long)NB * DHW2 / 2;   // field stride in uint2
    const int  DSU = HW2 / 2;              // d stride in uint2

#pragma unroll 5
    for (int i = 0; i < DL; ++i) {
        int dn = d0 + i + 4;
        W5 nf;
        if (dn < DD) {
            nf = wdrow(pc, tc, Sh, wq);
        } else {
#pragma unroll
            for (int f = 0; f < 5; ++f) { nf.h[f][0] = Z; nf.h[f][1] = Z; }
        }

        // D-conv (HFMA2) -> store
#pragma unroll
        for (int f = 0; f < 5; ++f) {
            __half2 y0 = __hmul2(G0h, win[f][0][0]);
            __half2 y1 = __hmul2(G0h, win[f][0][1]);
            y0 = __hfma2(G1h, win[f][1][0], y0); y1 = __hfma2(G1h, win[f][1][1], y1);
            y0 = __hfma2(G2h, win[f][2][0], y0); y1 = __hfma2(G2h, win[f][2][1], y1);
            y0 = __hfma2(G3h, win[f][3][0], y0); y1 = __hfma2(G3h, win[f][3][1], y1);
            y0 = __hfma2(G2h, win[f][4][0], y0); y1 = __hfma2(G2h, win[f][4][1], y1);
            y0 = __hfma2(G1h, win[f][5][0], y0); y1 = __hfma2(G1h, win[f][5][1], y1);
            y0 = __hfma2(G0h, win[f][6][0], y0); y1 = __hfma2(G0h, win[f][6][1], y1);
            uint2 o; o.x = h2u(y0); o.y = h2u(y1);
            dst[f * FS] = o;
        }

        // shift windows, push new row
#pragma unroll
        for (int f = 0; f < 5; ++f) {
#pragma unroll
            for (int k = 0; k < 6; ++k) {
                win[f][k][0] = win[f][k + 1][0];
                win[f][k][1] = win[f][k + 1][1];
            }
            win[f][6][0] = nf.h[f][0];
            win[f][6][1] = nf.h[f][1];
        }
        pc += HW_; tc += HW_; dst += DSU;
    }
}

// ---------------------------------------------------------------------------
// passH: streaming 7-tap H-conv (HFMA2) + exact border reconstruction +
// SSIM (f32x2) + block reduction + last-block final reduce.
// Thread = (n, d, w-pair, h-chunk of 32).
// ---------------------------------------------------------------------------
__global__ void __launch_bounds__(256) passH(float* __restrict__ out) {
    int tid = blockIdx.x * blockDim.x + threadIdx.x;   // 128,000 exactly
    int wp  = tid % 80;
    int rem = tid / 80;
    int ci  = rem % HCH;
    int rm2 = rem / HCH;
    int d   = rm2 % DD;
    int n   = rm2 / DD;
    int h0  = ci * HL;
    int w2  = 2 * wp;

    const __half2 Z = __float2half2_rn(0.f);
    const __half2 G0h = __float2half2_rn(G0c), G1h = __float2half2_rn(G1c);
    const __half2 G2h = __float2half2_rn(G2c), G3h = __float2half2_rn(G3c);
    const u64 K05 = pk(0.5f,0.5f), Kn025 = pk(-0.25f,-0.25f), K2 = pk(2.f,2.f);
    const u64 KC1 = pk(1e-4f,1e-4f), KC2 = pk(9e-4f,9e-4f), Kn1 = pk(-1.f,-1.f);

    float bd = bfac(d);
    u64 wwp = pk(bd * bfac(w2), bd * bfac(w2 + 1));

    const __half2* base[5];
#pragma unroll
    for (int f = 0; f < 5; ++f)
        base[f] = (const __half2*)g_buf2 + (long)(f * NB + n) * DHW2 +
                  (long)d * HW2 + wp;

    __half2 win[5][7];
#pragma unroll
    for (int k = 0; k < 7; ++k) {
        int row = h0 - 3 + k;
        bool v = (row >= 0) && (row < HH);
        int ro = (v ? row : 0) * 80;
#pragma unroll
        for (int f = 0; f < 5; ++f)
            win[f][k] = v ? base[f][ro] : Z;
    }

    float acc_ssim = 0.f;
    int po = (h0 + 4) * 80;

#pragma unroll 4
    for (int i = 0; i < HL; ++i) {
        int h = h0 + i;
        bool v = (h + 4 < HH);
        __half2 nxt[5];
#pragma unroll
        for (int f = 0; f < 5; ++f)
            nxt[f] = v ? base[f][po] : Z;

        u64 c[5];
#pragma unroll
        for (int f = 0; f < 5; ++f) {
            __half2 y = __hmul2(G0h, win[f][0]);
            y = __hfma2(G1h, win[f][1], y);
            y = __hfma2(G2h, win[f][2], y);
            y = __hfma2(G3h, win[f][3], y);
            y = __hfma2(G2h, win[f][4], y);
            y = __hfma2(G1h, win[f][5], y);
            y = __hfma2(G0h, win[f][6], y);
            float2 cf = __half22float2(y);
            c[f] = pk(cf.x, cf.y);
        }

        float bh = bfac(h);
        u64 W2  = mul2(wwp, pk(bh, bh));
        u64 mu1 = fma2(W2, K05, c[0]);
        u64 mu2 = fma2(W2, K05, c[1]);
        u64 Ep2 = fma2(W2, Kn025, add2(c[2], mu1));
        u64 Et2 = fma2(W2, Kn025, add2(c[3], mu2));
        u64 Ept = fma2(add2(mu1, mu2), K05, fma2(W2, Kn025, c[4]));
        u64 mu1s = mul2(mu1, mu1), mu2s = mul2(mu2, mu2), mu12 = mul2(mu1, mu2);
        u64 s1  = fma2(mu1s, Kn1, Ep2);
        u64 s2  = fma2(mu2s, Kn1, Et2);
        u64 s12 = fma2(mu12, Kn1, Ept);
        u64 num = mul2(fma2(mu12, K2, KC1), fma2(s12, K2, KC2));
        u64 den = mul2(add2(add2(mu1s, mu2s), KC1), add2(add2(s1, s2), KC2));
        float2 nf = upk(num), df = upk(den);
        acc_ssim += __fdividef(nf.x, df.x) + __fdividef(nf.y, df.y);

#pragma unroll
        for (int f = 0; f < 5; ++f) {
#pragma unroll
            for (int k = 0; k < 6; ++k) win[f][k] = win[f][k + 1];
            win[f][6] = nxt[f];
        }
        po += 80;
    }

    __shared__ float sred[256];
    __shared__ bool is_last;
    int lt = threadIdx.x;
    sred[lt] = acc_ssim;
    __syncthreads();
    for (int s = 128; s > 0; s >>= 1) {
        if (lt < s) sred[lt] += sred[lt + s];
        __syncthreads();
    }
    if (lt == 0) {
        g_partials[blockIdx.x] = sred[0];
        __threadfence();
        int v = atomicAdd(&g_ctr, 1);
        is_last = (v == (int)gridDim.x - 1);
    }
    __syncthreads();

    if (is_last) {
        __shared__ double sm[256];
        double acc = 0.0;
        for (int i = lt; i < NPART; i += 256) acc += (double)g_partials[i];
        sm[lt] = acc;
        __syncthreads();
        for (int s = 128; s > 0; s >>= 1) {
            if (lt < s) sm[lt] += sm[lt + s];
            __syncthreads();
        }
        if (lt == 0) {
            out[0] = 1.f - (float)(sm[0] / (double)NVOX);
            g_ctr = 0;   // reset for next graph replay
        }
    }
}

extern "C" void kernel_launch(void* const* d_in, const int* in_sizes, int n_in,
                              void* d_out, int out_size) {
    const float* p = (const float*)d_in[0];
    const float* t = (const float*)d_in[1];
    float* out = (float*)d_out;

    passWD<<<NWD / 128, 128>>>(p, t);   // 800 blocks, 102,400 threads
    passH<<<NPART, 256>>>(out);         // 500 blocks + folded final reduce
}

// round 11
// speedup vs baseline: 1.1831x; 1.1831x over previous
#include <cuda_runtime.h>
#include <cuda_fp16.h>

#define DD 160
#define HH 160
#define WW 160
#define NB 2
#define HW_ (HH * WW)
#define HW2 (HW_ / 2)
#define DHW_ (DD * HH * WW)          // 4,096,000
#define DHW2 (DHW_ / 2)
#define NVOX (NB * DHW_)             // 8,192,000
#define DCH 4
#define DL  (DD / DCH)               // 40
#define HCH 10
#define HL  (HH / HCH)               // 16
#define NPART 2000                   // passH blocks

#define G0c 0.0125602f
#define G1c 0.0788279f
#define G2c 0.2372961f
#define G3c 0.3426315f

typedef unsigned long long u64;

__device__ __forceinline__ float gk(int k) {
    constexpr float g[7] = {G0c, G1c, G2c, G3c, G2c, G1c, G0c};
    return g[k];
}
__device__ __forceinline__ u64 pk(float lo, float hi) {
    u64 r; asm("mov.b64 %0, {%1, %2};" : "=l"(r) : "f"(lo), "f"(hi)); return r;
}
__device__ __forceinline__ float2 upk(u64 v) {
    float2 r; asm("mov.b64 {%0, %1}, %2;" : "=f"(r.x), "=f"(r.y) : "l"(v)); return r;
}
__device__ __forceinline__ u64 fma2(u64 a, u64 b, u64 c) {
    u64 d; asm("fma.rn.f32x2 %0, %1, %2, %3;" : "=l"(d) : "l"(a), "l"(b), "l"(c)); return d;
}
__device__ __forceinline__ u64 mul2(u64 a, u64 b) {
    u64 d; asm("mul.rn.f32x2 %0, %1, %2;" : "=l"(d) : "l"(a), "l"(b)); return d;
}
__device__ __forceinline__ u64 add2(u64 a, u64 b) {
    u64 d; asm("add.rn.f32x2 %0, %1, %2;" : "=l"(d) : "l"(a), "l"(b)); return d;
}
__device__ __forceinline__ unsigned h2u(__half2 h) {
    return *reinterpret_cast<unsigned*>(&h);
}

// zero-padding valid-weight factor per axis
__device__ __forceinline__ float bfac(int i) {
    float f = 1.f;
    if (i < 3)   f -= (i == 2 ? G0c : (i == 1 ? (G0c + G1c) : (G0c + G1c + G2c)));
    if (i > 156) f -= (i == 157 ? G0c : (i == 158 ? (G0c + G1c) : (G0c + G1c + G2c)));
    return f;
}

// g_buf : planar [vol=f*NB+n][d][h][w] fp16 (passW out / passD in)
// g_buf2: field-interleaved [n][d][h][f][80*half2] fp16 (passD out / passH in)
__device__ __half g_buf[10u * DHW_];
__device__ __half g_buf2[10u * DHW_];
__device__ float g_partials[NPART];
__device__ int g_ctr;

// ---------------------------------------------------------------------------
// passW: 7-tap W-conv of the 5 shifted fields {q,r,q2,r2,qr}, q=p-1/2.
// Thread owns an 8-wide w-octet; 16-float neighborhood via 4+4 LDG.128;
// all in registers; one STG.128 (8 halves) per field. No smem. (R9-proven)
// ---------------------------------------------------------------------------
__global__ void __launch_bounds__(256) passW(const float* __restrict__ p,
                                             const float* __restrict__ t) {
    int tid = blockIdx.x * blockDim.x + threadIdx.x;   // 1,024,000
    int oct = tid % 20;
    int rem = tid / 20;
    int h   = rem % HH;
    int rm2 = rem / HH;
    int d   = rm2 % DD;
    int n   = rm2 / DD;
    int w0  = oct * 8;

    long rb = (long)n * DHW_ + ((long)d * HH + h) * WW + w0;
    const float4* p4 = (const float4*)(p + rb - 4);
    const float4* t4 = (const float4*)(t + rb - 4);
    const float4 z4 = {0.f, 0.f, 0.f, 0.f};

    float4 a0 = (oct > 0)  ? p4[0] : z4;
    float4 a1 = p4[1];
    float4 a2 = p4[2];
    float4 a3 = (oct < 19) ? p4[3] : z4;
    float4 b0 = (oct > 0)  ? t4[0] : z4;
    float4 b1 = t4[1];
    float4 b2 = t4[2];
    float4 b3 = (oct < 19) ? t4[3] : z4;

    float q[16], r[16];
    q[0]=a0.x-0.5f; q[1]=a0.y-0.5f; q[2]=a0.z-0.5f; q[3]=a0.w-0.5f;
    q[4]=a1.x-0.5f; q[5]=a1.y-0.5f; q[6]=a1.z-0.5f; q[7]=a1.w-0.5f;
    q[8]=a2.x-0.5f; q[9]=a2.y-0.5f; q[10]=a2.z-0.5f; q[11]=a2.w-0.5f;
    q[12]=a3.x-0.5f; q[13]=a3.y-0.5f; q[14]=a3.z-0.5f; q[15]=a3.w-0.5f;
    r[0]=b0.x-0.5f; r[1]=b0.y-0.5f; r[2]=b0.z-0.5f; r[3]=b0.w-0.5f;
    r[4]=b1.x-0.5f; r[5]=b1.y-0.5f; r[6]=b1.z-0.5f; r[7]=b1.w-0.5f;
    r[8]=b2.x-0.5f; r[9]=b2.y-0.5f; r[10]=b2.z-0.5f; r[11]=b2.w-0.5f;
    r[12]=b3.x-0.5f; r[13]=b3.y-0.5f; r[14]=b3.z-0.5f; r[15]=b3.w-0.5f;

    if (oct == 0)  { q[0]=q[1]=q[2]=q[3]=0.f;     r[0]=r[1]=r[2]=r[3]=0.f; }
    if (oct == 19) { q[12]=q[13]=q[14]=q[15]=0.f; r[12]=r[13]=r[14]=r[15]=0.f; }

    float acc[5][8];
#pragma unroll
    for (int f = 0; f < 5; ++f)
#pragma unroll
        for (int j = 0; j < 8; ++j) acc[f][j] = 0.f;

#pragma unroll
    for (int k = 0; k < 7; ++k) {
#pragma unroll
        for (int j = 0; j < 8; ++j) {
            float qa = q[1 + j + k], ra = r[1 + j + k];
            float g = gk(k);
            acc[0][j] = fmaf(g, qa, acc[0][j]);
            acc[1][j] = fmaf(g, ra, acc[1][j]);
            acc[2][j] = fmaf(g * qa, qa, acc[2][j]);
            acc[3][j] = fmaf(g * ra, ra, acc[3][j]);
            acc[4][j] = fmaf(g * qa, ra, acc[4][j]);
        }
    }

    long ob = rb / 8;
    uint4* outv = (uint4*)g_buf;
#pragma unroll
    for (int f = 0; f < 5; ++f) {
        uint4 v;
        v.x = h2u(__floats2half2_rn(acc[f][0], acc[f][1]));
        v.y = h2u(__floats2half2_rn(acc[f][2], acc[f][3]));
        v.z = h2u(__floats2half2_rn(acc[f][4], acc[f][5]));
        v.w = h2u(__floats2half2_rn(acc[f][6], acc[f][7]));
        outv[(long)(f * NB) * (DHW_ / 8) + ob] = v;
    }
}

// ---------------------------------------------------------------------------
// passD: streaming 7-tap D-conv in HFMA2, 4 voxels (uint2) per thread-step.
// Reads planar g_buf; writes field-interleaved g_buf2. No smem. (R9-proven,
// only the store indexing changed.)
// ---------------------------------------------------------------------------
__global__ void __launch_bounds__(256) passD() {
    int tid = blockIdx.x * blockDim.x + threadIdx.x;   // 256,000
    int wq  = tid % 40;
    int rem = tid / 40;
    int ci  = rem % DCH;
    int rm2 = rem / DCH;
    int h   = rm2 % HH;
    int vol = rm2 / HH;
    int d0  = ci * DL;
    int f   = vol >> 1;          // vol = f*NB + n
    int n   = vol & 1;

    const uint2* src = (const uint2*)g_buf + (long)vol * (DHW_ / 4) + (long)h * 40 + wq;
    // interleaved dst: uint2 index = ((n*DD + d)*HH + h)*200 + f*40 + wq
    uint2* dst = (uint2*)g_buf2 + (((long)n * DD + d0) * HH + h) * 200 + f * 40 + wq;
    const int DS  = HW_ / 4;     // src d-stride (uint2)
    const int DSO = HH * 200;    // dst d-stride (uint2)

    const __half2 Z = __float2half2_rn(0.f);
    const __half2 G0h = __float2half2_rn(G0c), G1h = __float2half2_rn(G1c);
    const __half2 G2h = __float2half2_rn(G2c), G3h = __float2half2_rn(G3c);

    __half2 wa[7], wb[7];
#pragma unroll
    for (int k = 0; k < 7; ++k) {
        int dd = d0 - 3 + k;
        if (dd >= 0 && dd < DD) {
            uint2 v = src[(long)dd * DS];
            wa[k] = *(__half2*)&v.x;
            wb[k] = *(__half2*)&v.y;
        } else { wa[k] = Z; wb[k] = Z; }
    }

    const uint2* sp = src + (long)(d0 + 4) * DS;

#pragma unroll 4
    for (int i = 0; i < DL; ++i) {
        int dn = d0 + i + 4;
        __half2 na = Z, nb = Z;
        if (dn < DD) {
            uint2 v = *sp;
            na = *(__half2*)&v.x;
            nb = *(__half2*)&v.y;
        }
        __half2 ya = __hmul2(G0h, wa[0]);
        ya = __hfma2(G1h, wa[1], ya); ya = __hfma2(G2h, wa[2], ya);
        ya = __hfma2(G3h, wa[3], ya); ya = __hfma2(G2h, wa[4], ya);
        ya = __hfma2(G1h, wa[5], ya); ya = __hfma2(G0h, wa[6], ya);
        __half2 yb = __hmul2(G0h, wb[0]);
        yb = __hfma2(G1h, wb[1], yb); yb = __hfma2(G2h, wb[2], yb);
        yb = __hfma2(G3h, wb[3], yb); yb = __hfma2(G2h, wb[4], yb);
        yb = __hfma2(G1h, wb[5], yb); yb = __hfma2(G0h, wb[6], yb);
        uint2 o; o.x = h2u(ya); o.y = h2u(yb);
        *dst = o;
#pragma unroll
        for (int k = 0; k < 6; ++k) { wa[k] = wa[k + 1]; wb[k] = wb[k + 1]; }
        wa[6] = na; wb[6] = nb;
        sp += DS; dst += DSO;
    }
}

// ---------------------------------------------------------------------------
// passH: streaming 7-tap H-conv (HFMA2) with depth-2 row prefetch + exact
// border reconstruction + SSIM (f32x2) + block reduce + last-block reduce.
// Thread = (n, d, w-pair, h-chunk of 16). Field-interleaved loads: single
// base pointer + immediate offsets.
// ---------------------------------------------------------------------------
__global__ void __launch_bounds__(128, 5) passH(float* __restrict__ out) {
    int tid = blockIdx.x * blockDim.x + threadIdx.x;   // 256,000 exactly
    int wp  = tid % 80;
    int rem = tid / 80;
    int ci  = rem % HCH;
    int rm2 = rem / HCH;
    int d   = rm2 % DD;
    int n   = rm2 / DD;
    int h0  = ci * HL;
    int w2  = 2 * wp;

    const __half2 Z = __float2half2_rn(0.f);
    const __half2 G0h = __float2half2_rn(G0c), G1h = __float2half2_rn(G1c);
    const __half2 G2h = __float2half2_rn(G2c), G3h = __float2half2_rn(G3c);
    const u64 K05 = pk(0.5f,0.5f), Kn025 = pk(-0.25f,-0.25f), K2 = pk(2.f,2.f);
    const u64 KC1 = pk(1e-4f,1e-4f), KC2 = pk(9e-4f,9e-4f), Kn1 = pk(-1.f,-1.f);

    float bd = bfac(d);
    u64 wwp = pk(bd * bfac(w2), bd * bfac(w2 + 1));

    // row r, field f at: base + r*400 + f*80   (half2 units; f*320B = imm)
    const __half2* base = (const __half2*)g_buf2 +
                          (((long)n * DD + d) * HH) * 400 + wp;

    __half2 win[5][7];
#pragma unroll
    for (int k = 0; k < 7; ++k) {
        int row = h0 - 3 + k;
        bool v = (row >= 0) && (row < HH);
        const __half2* rp = base + (long)(v ? row : 0) * 400;
#pragma unroll
        for (int f = 0; f < 5; ++f)
            win[f][k] = v ? rp[f * 80] : Z;
    }

    // depth-2 prefetch: P1 = row h0+4, P2 = row h0+5
    __half2 P1[5], P2[5];
    {
        bool v1 = (h0 + 4 < HH), v2 = (h0 + 5 < HH);
        const __half2* r1 = base + (long)(v1 ? h0 + 4 : 0) * 400;
        const __half2* r2 = base + (long)(v2 ? h0 + 5 : 0) * 400;
#pragma unroll
        for (int f = 0; f < 5; ++f) {
            P1[f] = v1 ? r1[f * 80] : Z;
            P2[f] = v2 ? r2[f * 80] : Z;
        }
    }

    float acc_ssim = 0.f;

#pragma unroll 4
    for (int i = 0; i < HL; ++i) {
        int h = h0 + i;

        u64 c[5];
#pragma unroll
        for (int f = 0; f < 5; ++f) {
            __half2 y = __hmul2(G0h, win[f][0]);
            y = __hfma2(G1h, win[f][1], y);
            y = __hfma2(G2h, win[f][2], y);
            y = __hfma2(G3h, win[f][3], y);
            y = __hfma2(G2h, win[f][4], y);
            y = __hfma2(G1h, win[f][5], y);
            y = __hfma2(G0h, win[f][6], y);
            float2 cf = __half22float2(y);
            c[f] = pk(cf.x, cf.y);
        }

        float bh = bfac(h);
        u64 W2  = mul2(wwp, pk(bh, bh));
        u64 mu1 = fma2(W2, K05, c[0]);
        u64 mu2 = fma2(W2, K05, c[1]);
        u64 Ep2 = fma2(W2, Kn025, add2(c[2], mu1));
        u64 Et2 = fma2(W2, Kn025, add2(c[3], mu2));
        u64 Ept = fma2(add2(mu1, mu2), K05, fma2(W2, Kn025, c[4]));
        u64 mu1s = mul2(mu1, mu1), mu2s = mul2(mu2, mu2), mu12 = mul2(mu1, mu2);
        u64 s1  = fma2(mu1s, Kn1, Ep2);
        u64 s2  = fma2(mu2s, Kn1, Et2);
        u64 s12 = fma2(mu12, Kn1, Ept);
        u64 num = mul2(fma2(mu12, K2, KC1), fma2(s12, K2, KC2));
        u64 den = mul2(add2(add2(mu1s, mu2s), KC1), add2(add2(s1, s2), KC2));
        float2 nf = upk(num), df = upk(den);
        acc_ssim += __fdividef(nf.x, df.x) + __fdividef(nf.y, df.y);

        // shift window, insert P1; P1 <- P2; issue P2 load (row h+6)
        bool v = (h + 6 < HH);
        const __half2* rp = base + (long)(v ? h + 6 : 0) * 400;
#pragma unroll
        for (int f = 0; f < 5; ++f) {
#pragma unroll
            for (int k = 0; k < 6; ++k) win[f][k] = win[f][k + 1];
            win[f][6] = P1[f];
            P1[f] = P2[f];
            P2[f] = v ? rp[f * 80] : Z;
        }
    }

    __shared__ float sred[128];
    __shared__ bool is_last;
    int lt = threadIdx.x;
    sred[lt] = acc_ssim;
    __syncthreads();
    for (int s = 64; s > 0; s >>= 1) {
        if (lt < s) sred[lt] += sred[lt + s];
        __syncthreads();
    }
    if (lt == 0) {
        g_partials[blockIdx.x] = sred[0];
        __threadfence();
        int v = atomicAdd(&g_ctr, 1);
        is_last = (v == (int)gridDim.x - 1);
    }
    __syncthreads();

    if (is_last) {
        __shared__ double sm[128];
        double acc = 0.0;
        for (int i = lt; i < NPART; i += 128) acc += (double)g_partials[i];
        sm[lt] = acc;
        __syncthreads();
        for (int s = 64; s > 0; s >>= 1) {
            if (lt < s) sm[lt] += sm[lt + s];
            __syncthreads();
        }
        if (lt == 0) {
            out[0] = 1.f - (float)(sm[0] / (double)NVOX);
            g_ctr = 0;   // reset for next graph replay
        }
    }
}

extern "C" void kernel_launch(void* const* d_in, const int* in_sizes, int n_in,
                              void* d_out, int out_size) {
    const float* p = (const float*)d_in[0];
    const float* t = (const float*)d_in[1];
    float* out = (float*)d_out;

    passW<<<4000, 256>>>(p, t);     // 1,024,000 threads
    passD<<<1000, 256>>>();         //   256,000 threads (4 voxels/step)
    passH<<<NPART, 128>>>(out);     //   256,000 threads + folded reduce
}

// round 12
// speedup vs baseline: 1.2086x; 1.0216x over previous
#include <cuda_runtime.h>
#include <cuda_fp16.h>

#define DD 160
#define HH 160
#define WW 160
#define NB 2
#define HW_ (HH * WW)
#define HW2 (HW_ / 2)
#define DHW_ (DD * HH * WW)          // 4,096,000
#define DHW2 (DHW_ / 2)
#define NVOX (NB * DHW_)             // 8,192,000
#define DCH 4
#define DL  (DD / DCH)               // 40
#define HCH 10
#define HL  (HH / HCH)               // 16
#define NPART 2000                   // passH blocks

#define G0c 0.0125602f
#define G1c 0.0788279f
#define G2c 0.2372961f
#define G3c 0.3426315f

typedef unsigned long long u64;

__device__ __forceinline__ float gk(int k) {
    constexpr float g[7] = {G0c, G1c, G2c, G3c, G2c, G1c, G0c};
    return g[k];
}
__device__ __forceinline__ u64 pk(float lo, float hi) {
    u64 r; asm("mov.b64 %0, {%1, %2};" : "=l"(r) : "f"(lo), "f"(hi)); return r;
}
__device__ __forceinline__ float2 upk(u64 v) {
    float2 r; asm("mov.b64 {%0, %1}, %2;" : "=f"(r.x), "=f"(r.y) : "l"(v)); return r;
}
__device__ __forceinline__ u64 fma2(u64 a, u64 b, u64 c) {
    u64 d; asm("fma.rn.f32x2 %0, %1, %2, %3;" : "=l"(d) : "l"(a), "l"(b), "l"(c)); return d;
}
__device__ __forceinline__ u64 mul2(u64 a, u64 b) {
    u64 d; asm("mul.rn.f32x2 %0, %1, %2;" : "=l"(d) : "l"(a), "l"(b)); return d;
}
__device__ __forceinline__ u64 add2(u64 a, u64 b) {
    u64 d; asm("add.rn.f32x2 %0, %1, %2;" : "=l"(d) : "l"(a), "l"(b)); return d;
}
__device__ __forceinline__ unsigned h2u(__half2 h) {
    return *reinterpret_cast<unsigned*>(&h);
}

// zero-padding valid-weight factor per axis
__device__ __forceinline__ float bfac(int i) {
    float f = 1.f;
    if (i < 3)   f -= (i == 2 ? G0c : (i == 1 ? (G0c + G1c) : (G0c + G1c + G2c)));
    if (i > 156) f -= (i == 157 ? G0c : (i == 158 ? (G0c + G1c) : (G0c + G1c + G2c)));
    return f;
}

// g_buf : planar [vol=f*NB+n][d][h][w] fp16 (passW out / passD in)
// g_buf2: field-interleaved [n][d][h][f][80*half2] fp16 (passD out / passH in)
__device__ __half g_buf[10u * DHW_];
__device__ __half g_buf2[10u * DHW_];
__device__ float g_partials[NPART];
__device__ int g_ctr;

// ---------------------------------------------------------------------------
// passW: 7-tap W-conv of the 5 shifted fields {q,r,q2,r2,qr}, q=p-1/2.
// Thread owns an 8-wide w-octet. Scatter form: for each of the 14 used taps,
// compute the 3 products once, then FFMA-imm into the covered outputs.
// ---------------------------------------------------------------------------
__global__ void __launch_bounds__(256) passW(const float* __restrict__ p,
                                             const float* __restrict__ t) {
    int tid = blockIdx.x * blockDim.x + threadIdx.x;   // 1,024,000
    int oct = tid % 20;
    int rem = tid / 20;
    int h   = rem % HH;
    int rm2 = rem / HH;
    int d   = rm2 % DD;
    int n   = rm2 / DD;
    int w0  = oct * 8;

    long rb = (long)n * DHW_ + ((long)d * HH + h) * WW + w0;
    const float4* p4 = (const float4*)(p + rb - 4);
    const float4* t4 = (const float4*)(t + rb - 4);
    const float4 z4 = {0.f, 0.f, 0.f, 0.f};

    float4 a0 = (oct > 0)  ? p4[0] : z4;
    float4 a1 = p4[1];
    float4 a2 = p4[2];
    float4 a3 = (oct < 19) ? p4[3] : z4;
    float4 b0 = (oct > 0)  ? t4[0] : z4;
    float4 b1 = t4[1];
    float4 b2 = t4[2];
    float4 b3 = (oct < 19) ? t4[3] : z4;

    // taps 1..14 cover w = w0-3 .. w0+10 (taps 0 and 15 are never used)
    float q[16], r[16];
    q[0]=0.f;       q[1]=a0.y-0.5f; q[2]=a0.z-0.5f; q[3]=a0.w-0.5f;
    q[4]=a1.x-0.5f; q[5]=a1.y-0.5f; q[6]=a1.z-0.5f; q[7]=a1.w-0.5f;
    q[8]=a2.x-0.5f; q[9]=a2.y-0.5f; q[10]=a2.z-0.5f; q[11]=a2.w-0.5f;
    q[12]=a3.x-0.5f; q[13]=a3.y-0.5f; q[14]=a3.z-0.5f; q[15]=0.f;
    r[0]=0.f;       r[1]=b0.y-0.5f; r[2]=b0.z-0.5f; r[3]=b0.w-0.5f;
    r[4]=b1.x-0.5f; r[5]=b1.y-0.5f; r[6]=b1.z-0.5f; r[7]=b1.w-0.5f;
    r[8]=b2.x-0.5f; r[9]=b2.y-0.5f; r[10]=b2.z-0.5f; r[11]=b2.w-0.5f;
    r[12]=b3.x-0.5f; r[13]=b3.y-0.5f; r[14]=b3.z-0.5f; r[15]=0.f;

    // out-of-range field taps must be exactly 0 (the -0.5 shift must not leak)
    if (oct == 0)  { q[1]=q[2]=q[3]=0.f;    r[1]=r[2]=r[3]=0.f; }
    if (oct == 19) { q[12]=q[13]=q[14]=0.f; r[12]=r[13]=r[14]=0.f; }

    float c0[8], c1[8], c2[8], c3[8], c4[8];
#pragma unroll
    for (int j = 0; j < 8; ++j) { c0[j]=0.f; c1[j]=0.f; c2[j]=0.f; c3[j]=0.f; c4[j]=0.f; }

#pragma unroll
    for (int i = 1; i < 15; ++i) {
        float qi = q[i], ri = r[i];
        float qq = qi * qi, rr = ri * ri, pr = qi * ri;
#pragma unroll
        for (int j = 0; j < 8; ++j) {
            const int k = i - 1 - j;
            if (k >= 0 && k < 7) {
                const float g = gk(k);    // compile-time literal -> FFMA-imm
                c0[j] = fmaf(g, qi, c0[j]);
                c1[j] = fmaf(g, ri, c1[j]);
                c2[j] = fmaf(g, qq, c2[j]);
                c3[j] = fmaf(g, rr, c3[j]);
                c4[j] = fmaf(g, pr, c4[j]);
            }
        }
    }

    long ob = rb / 8;
    uint4* outv = (uint4*)g_buf;
    {
        uint4 v;
        v.x = h2u(__floats2half2_rn(c0[0], c0[1]));
        v.y = h2u(__floats2half2_rn(c0[2], c0[3]));
        v.z = h2u(__floats2half2_rn(c0[4], c0[5]));
        v.w = h2u(__floats2half2_rn(c0[6], c0[7]));
        outv[(long)(0 * NB) * (DHW_ / 8) + ob] = v;
        v.x = h2u(__floats2half2_rn(c1[0], c1[1]));
        v.y = h2u(__floats2half2_rn(c1[2], c1[3]));
        v.z = h2u(__floats2half2_rn(c1[4], c1[5]));
        v.w = h2u(__floats2half2_rn(c1[6], c1[7]));
        outv[(long)(1 * NB) * (DHW_ / 8) + ob] = v;
        v.x = h2u(__floats2half2_rn(c2[0], c2[1]));
        v.y = h2u(__floats2half2_rn(c2[2], c2[3]));
        v.z = h2u(__floats2half2_rn(c2[4], c2[5]));
        v.w = h2u(__floats2half2_rn(c2[6], c2[7]));
        outv[(long)(2 * NB) * (DHW_ / 8) + ob] = v;
        v.x = h2u(__floats2half2_rn(c3[0], c3[1]));
        v.y = h2u(__floats2half2_rn(c3[2], c3[3]));
        v.z = h2u(__floats2half2_rn(c3[4], c3[5]));
        v.w = h2u(__floats2half2_rn(c3[6], c3[7]));
        outv[(long)(3 * NB) * (DHW_ / 8) + ob] = v;
        v.x = h2u(__floats2half2_rn(c4[0], c4[1]));
        v.y = h2u(__floats2half2_rn(c4[2], c4[3]));
        v.z = h2u(__floats2half2_rn(c4[4], c4[5]));
        v.w = h2u(__floats2half2_rn(c4[6], c4[7]));
        outv[(long)(4 * NB) * (DHW_ / 8) + ob] = v;
    }
}

// ---------------------------------------------------------------------------
// passD: streaming 7-tap D-conv in HFMA2, 8 voxels (uint4) per thread-step.
// Reads planar g_buf; writes field-interleaved g_buf2. No smem.
// ---------------------------------------------------------------------------
__global__ void __launch_bounds__(256) passD() {
    int tid = blockIdx.x * blockDim.x + threadIdx.x;   // 128,000
    int wq  = tid % 20;              // uint4 lane in row
    int rem = tid / 20;
    int ci  = rem % DCH;
    int rm2 = rem / DCH;
    int h   = rm2 % HH;
    int vol = rm2 / HH;
    int d0  = ci * DL;
    int f   = vol >> 1;              // vol = f*NB + n
    int n   = vol & 1;

    const uint4* src = (const uint4*)g_buf + (long)vol * (DHW_ / 8) + (long)h * 20 + wq;
    uint4* dst = (uint4*)g_buf2 + (((long)n * DD + d0) * HH + h) * 100 + f * 20 + wq;
    const int DS  = HW_ / 8;         // src d-stride (uint4) = 3200
    const int DSO = HH * 100;        // dst d-stride (uint4) = 16000

    const __half2 Z = __float2half2_rn(0.f);
    const __half2 G0h = __float2half2_rn(G0c), G1h = __float2half2_rn(G1c);
    const __half2 G2h = __float2half2_rn(G2c), G3h = __float2half2_rn(G3c);

    __half2 w0[7], w1[7], w2[7], w3[7];
#pragma unroll
    for (int k = 0; k < 7; ++k) {
        int dd = d0 - 3 + k;
        if (dd >= 0 && dd < DD) {
            uint4 v = src[(long)dd * DS];
            w0[k] = *(__half2*)&v.x; w1[k] = *(__half2*)&v.y;
            w2[k] = *(__half2*)&v.z; w3[k] = *(__half2*)&v.w;
        } else { w0[k] = Z; w1[k] = Z; w2[k] = Z; w3[k] = Z; }
    }

    const uint4* sp = src + (long)(d0 + 4) * DS;

#pragma unroll 4
    for (int i = 0; i < DL; ++i) {
        int dn = d0 + i + 4;
        __half2 n0 = Z, n1 = Z, n2 = Z, n3 = Z;
        if (dn < DD) {
            uint4 v = *sp;
            n0 = *(__half2*)&v.x; n1 = *(__half2*)&v.y;
            n2 = *(__half2*)&v.z; n3 = *(__half2*)&v.w;
        }
        __half2 y0 = __hmul2(G0h, w0[0]);
        __half2 y1 = __hmul2(G0h, w1[0]);
        __half2 y2 = __hmul2(G0h, w2[0]);
        __half2 y3 = __hmul2(G0h, w3[0]);
        y0 = __hfma2(G1h, w0[1], y0); y1 = __hfma2(G1h, w1[1], y1);
        y2 = __hfma2(G1h, w2[1], y2); y3 = __hfma2(G1h, w3[1], y3);
        y0 = __hfma2(G2h, w0[2], y0); y1 = __hfma2(G2h, w1[2], y1);
        y2 = __hfma2(G2h, w2[2], y2); y3 = __hfma2(G2h, w3[2], y3);
        y0 = __hfma2(G3h, w0[3], y0); y1 = __hfma2(G3h, w1[3], y1);
        y2 = __hfma2(G3h, w2[3], y2); y3 = __hfma2(G3h, w3[3], y3);
        y0 = __hfma2(G2h, w0[4], y0); y1 = __hfma2(G2h, w1[4], y1);
        y2 = __hfma2(G2h, w2[4], y2); y3 = __hfma2(G2h, w3[4], y3);
        y0 = __hfma2(G1h, w0[5], y0); y1 = __hfma2(G1h, w1[5], y1);
        y2 = __hfma2(G1h, w2[5], y2); y3 = __hfma2(G1h, w3[5], y3);
        y0 = __hfma2(G0h, w0[6], y0); y1 = __hfma2(G0h, w1[6], y1);
        y2 = __hfma2(G0h, w2[6], y2); y3 = __hfma2(G0h, w3[6], y3);
        uint4 o;
        o.x = h2u(y0); o.y = h2u(y1); o.z = h2u(y2); o.w = h2u(y3);
        *dst = o;
#pragma unroll
        for (int k = 0; k < 6; ++k) {
            w0[k] = w0[k + 1]; w1[k] = w1[k + 1];
            w2[k] = w2[k + 1]; w3[k] = w3[k + 1];
        }
        w0[6] = n0; w1[6] = n1; w2[6] = n2; w3[6] = n3;
        sp += DS; dst += DSO;
    }
}

// ---------------------------------------------------------------------------
// passH: streaming 7-tap H-conv (HFMA2) with depth-2 row prefetch + exact
// border reconstruction + SSIM (f32x2) + block reduce + last-block reduce.
// Thread = (n, d, w-pair, h-chunk of 16). Field-interleaved loads. (R11)
// ---------------------------------------------------------------------------
__global__ void __launch_bounds__(128, 5) passH(float* __restrict__ out) {
    int tid = blockIdx.x * blockDim.x + threadIdx.x;   // 256,000 exactly
    int wp  = tid % 80;
    int rem = tid / 80;
    int ci  = rem % HCH;
    int rm2 = rem / HCH;
    int d   = rm2 % DD;
    int n   = rm2 / DD;
    int h0  = ci * HL;
    int w2  = 2 * wp;

    const __half2 Z = __float2half2_rn(0.f);
    const __half2 G0h = __float2half2_rn(G0c), G1h = __float2half2_rn(G1c);
    const __half2 G2h = __float2half2_rn(G2c), G3h = __float2half2_rn(G3c);
    const u64 K05 = pk(0.5f,0.5f), Kn025 = pk(-0.25f,-0.25f), K2 = pk(2.f,2.f);
    const u64 KC1 = pk(1e-4f,1e-4f), KC2 = pk(9e-4f,9e-4f), Kn1 = pk(-1.f,-1.f);

    float bd = bfac(d);
    u64 wwp = pk(bd * bfac(w2), bd * bfac(w2 + 1));

    const __half2* base = (const __half2*)g_buf2 +
                          (((long)n * DD + d) * HH) * 400 + wp;

    __half2 win[5][7];
#pragma unroll
    for (int k = 0; k < 7; ++k) {
        int row = h0 - 3 + k;
        bool v = (row >= 0) && (row < HH);
        const __half2* rp = base + (long)(v ? row : 0) * 400;
#pragma unroll
        for (int f = 0; f < 5; ++f)
            win[f][k] = v ? rp[f * 80] : Z;
    }

    __half2 P1[5], P2[5];
    {
        bool v1 = (h0 + 4 < HH), v2 = (h0 + 5 < HH);
        const __half2* r1 = base + (long)(v1 ? h0 + 4 : 0) * 400;
        const __half2* r2 = base + (long)(v2 ? h0 + 5 : 0) * 400;
#pragma unroll
        for (int f = 0; f < 5; ++f) {
            P1[f] = v1 ? r1[f * 80] : Z;
            P2[f] = v2 ? r2[f * 80] : Z;
        }
    }

    float acc_ssim = 0.f;

#pragma unroll 4
    for (int i = 0; i < HL; ++i) {
        int h = h0 + i;

        u64 c[5];
#pragma unroll
        for (int f = 0; f < 5; ++f) {
            __half2 y = __hmul2(G0h, win[f][0]);
            y = __hfma2(G1h, win[f][1], y);
            y = __hfma2(G2h, win[f][2], y);
            y = __hfma2(G3h, win[f][3], y);
            y = __hfma2(G2h, win[f][4], y);
            y = __hfma2(G1h, win[f][5], y);
            y = __hfma2(G0h, win[f][6], y);
            float2 cf = __half22float2(y);
            c[f] = pk(cf.x, cf.y);
        }

        float bh = bfac(h);
        u64 W2  = mul2(wwp, pk(bh, bh));
        u64 mu1 = fma2(W2, K05, c[0]);
        u64 mu2 = fma2(W2, K05, c[1]);
        u64 Ep2 = fma2(W2, Kn025, add2(c[2], mu1));
        u64 Et2 = fma2(W2, Kn025, add2(c[3], mu2));
        u64 Ept = fma2(add2(mu1, mu2), K05, fma2(W2, Kn025, c[4]));
        u64 mu1s = mul2(mu1, mu1), mu2s = mul2(mu2, mu2), mu12 = mul2(mu1, mu2);
        u64 s1  = fma2(mu1s, Kn1, Ep2);
        u64 s2  = fma2(mu2s, Kn1, Et2);
        u64 s12 = fma2(mu12, Kn1, Ept);
        u64 num = mul2(fma2(mu12, K2, KC1), fma2(s12, K2, KC2));
        u64 den = mul2(add2(add2(mu1s, mu2s), KC1), add2(add2(s1, s2), KC2));
        float2 nf = upk(num), df = upk(den);
        acc_ssim += __fdividef(nf.x, df.x) + __fdividef(nf.y, df.y);

        bool v = (h + 6 < HH);
        const __half2* rp = base + (long)(v ? h + 6 : 0) * 400;
#pragma unroll
        for (int f = 0; f < 5; ++f) {
#pragma unroll
            for (int k = 0; k < 6; ++k) win[f][k] = win[f][k + 1];
            win[f][6] = P1[f];
            P1[f] = P2[f];
            P2[f] = v ? rp[f * 80] : Z;
        }
    }

    __shared__ float sred[128];
    __shared__ bool is_last;
    int lt = threadIdx.x;
    sred[lt] = acc_ssim;
    __syncthreads();
    for (int s = 64; s > 0; s >>= 1) {
        if (lt < s) sred[lt] += sred[lt + s];
        __syncthreads();
    }
    if (lt == 0) {
        g_partials[blockIdx.x] = sred[0];
        __threadfence();
        int v = atomicAdd(&g_ctr, 1);
        is_last = (v == (int)gridDim.x - 1);
    }
    __syncthreads();

    if (is_last) {
        __shared__ double sm[128];
        double acc = 0.0;
        for (int i = lt; i < NPART; i += 128) acc += (double)g_partials[i];
        sm[lt] = acc;
        __syncthreads();
        for (int s = 64; s > 0; s >>= 1) {
            if (lt < s) sm[lt] += sm[lt + s];
            __syncthreads();
        }
        if (lt == 0) {
            out[0] = 1.f - (float)(sm[0] / (double)NVOX);
            g_ctr = 0;   // reset for next graph replay
        }
    }
}

extern "C" void kernel_launch(void* const* d_in, const int* in_sizes, int n_in,
                              void* d_out, int out_size) {
    const float* p = (const float*)d_in[0];
    const float* t = (const float*)d_in[1];
    float* out = (float*)d_out;

    passW<<<4000, 256>>>(p, t);     // 1,024,000 threads
    passD<<<500, 256>>>();          //   128,000 threads (8 voxels/step)
    passH<<<NPART, 128>>>(out);     //   256,000 threads + folded reduce
}